// round 15
// baseline (speedup 1.0000x reference)
#include <cuda_runtime.h>
#include <cuda_bf16.h>
#include <cstdint>
#include <math.h>

#define NB 128
#define NT 8
#define ND 2048
#define NR 4
#define NV 512
#define NN 8192   // V*R*R

// ---------------- scratch (no allocation allowed) ----------------
__device__ __nv_bfloat16 g_xbar[NB * ND];   // mean over T, bf16
__device__ float g_alpha[NB * NR];
__device__ float g_beta[NB * NR];
__device__ float g_part0[NB * NN];          // signed partial (K 0..1023)
__device__ float g_part1[NB * NN];          // signed partial (K 1024..2047)
__device__ float g_loss[NB];
__device__ int g_done_cnt;                  // zero-init; self-resetting

// =================================================================
// Kernel A: xbar = mean_t(input_embs), alpha/beta = |xbar @ w_{a,b}|
// (proven 6.8us)
// =================================================================
__global__ __launch_bounds__(512) void prep_kernel(
    const float* __restrict__ x, const float* __restrict__ wa,
    const float* __restrict__ wb) {
  const int b = blockIdx.x;
  const int tid = threadIdx.x;
  const int lane = tid & 31;
  const int warp = tid >> 5;
  const int d4 = tid * 4;
  const float* xb = x + (size_t)b * NT * ND + d4;

  float4 v[NT];
#pragma unroll
  for (int t = 0; t < NT; t++)
    v[t] = *reinterpret_cast<const float4*>(xb + t * ND);
  float4 s4;
  s4.x = (((v[0].x + v[1].x) + (v[2].x + v[3].x)) +
          ((v[4].x + v[5].x) + (v[6].x + v[7].x))) * 0.125f;
  s4.y = (((v[0].y + v[1].y) + (v[2].y + v[3].y)) +
          ((v[4].y + v[5].y) + (v[6].y + v[7].y))) * 0.125f;
  s4.z = (((v[0].z + v[1].z) + (v[2].z + v[3].z)) +
          ((v[4].z + v[5].z) + (v[6].z + v[7].z))) * 0.125f;
  s4.w = (((v[0].w + v[1].w) + (v[2].w + v[3].w)) +
          ((v[4].w + v[5].w) + (v[6].w + v[7].w))) * 0.125f;

  __nv_bfloat162 lo = __floats2bfloat162_rn(s4.x, s4.y);
  __nv_bfloat162 hi = __floats2bfloat162_rn(s4.z, s4.w);
  uint2 packed;
  packed.x = *reinterpret_cast<unsigned*>(&lo);
  packed.y = *reinterpret_cast<unsigned*>(&hi);
  *reinterpret_cast<uint2*>(&g_xbar[b * ND + d4]) = packed;

  float p[8] = {0.f, 0.f, 0.f, 0.f, 0.f, 0.f, 0.f, 0.f};
#pragma unroll
  for (int q = 0; q < 4; q++) {
    const float sd = (&s4.x)[q];
    float4 a4 = *reinterpret_cast<const float4*>(wa + (d4 + q) * 4);
    float4 b4 = *reinterpret_cast<const float4*>(wb + (d4 + q) * 4);
    p[0] += sd * a4.x; p[1] += sd * a4.y; p[2] += sd * a4.z; p[3] += sd * a4.w;
    p[4] += sd * b4.x; p[5] += sd * b4.y; p[6] += sd * b4.z; p[7] += sd * b4.w;
  }

  __shared__ float sred[16][8];
#pragma unroll
  for (int q = 0; q < 8; q++) {
    float vv = p[q];
#pragma unroll
    for (int o = 16; o; o >>= 1) vv += __shfl_xor_sync(0xFFFFFFFFu, vv, o);
    if (lane == 0) sred[warp][q] = vv;
  }
  __syncthreads();
  if (tid < 8) {
    float s = 0.f;
#pragma unroll
    for (int w = 0; w < 16; w++) s += sred[w][tid];
    s = fabsf(s);
    if (tid < 4) g_alpha[b * 4 + tid] = s;
    else         g_beta[b * 4 + (tid - 4)] = s;
  }
}

// =================================================================
// Kernel B: split-K GEMM with cp.async 3-stage pipeline.
// 256 blocks (128 n-tiles x 2 k-halves), 256 threads, 2 CTAs/SM.
// A: bf16 in smem (swizzled, ldmatrix). B: fp32 in smem (pitch 272B,
// conflict-free LDS.32 fragment loads + cvt to bf16).
// =================================================================
__device__ __forceinline__ void ldsm_x4(unsigned& r0, unsigned& r1,
                                        unsigned& r2, unsigned& r3,
                                        unsigned addr) {
  asm volatile("ldmatrix.sync.aligned.m8n8.x4.shared.b16 {%0,%1,%2,%3}, [%4];"
               : "=r"(r0), "=r"(r1), "=r"(r2), "=r"(r3) : "r"(addr));
}
__device__ __forceinline__ void mma16816(float& c0, float& c1, float& c2, float& c3,
                                         unsigned a0, unsigned a1, unsigned a2,
                                         unsigned a3, unsigned b0, unsigned b1) {
  asm volatile(
      "mma.sync.aligned.m16n8k16.row.col.f32.bf16.bf16.f32 "
      "{%0,%1,%2,%3}, {%4,%5,%6,%7}, {%8,%9}, {%0,%1,%2,%3};"
      : "+f"(c0), "+f"(c1), "+f"(c2), "+f"(c3)
      : "r"(a0), "r"(a1), "r"(a2), "r"(a3), "r"(b0), "r"(b1));
}
__device__ __forceinline__ void cpasync16(unsigned dst, const void* src) {
  asm volatile("cp.async.cg.shared.global [%0], [%1], 16;"
               :: "r"(dst), "l"(src) : "memory");
}
__device__ __forceinline__ void cpcommit() {
  asm volatile("cp.async.commit_group;" ::: "memory");
}
template <int N>
__device__ __forceinline__ void cpwait() {
  asm volatile("cp.async.wait_group %0;" :: "n"(N) : "memory");
}
__device__ __forceinline__ float lds_f32(unsigned addr) {
  float v;
  asm volatile("ld.shared.f32 %0, [%1];" : "=f"(v) : "r"(addr));
  return v;
}

#define A_ST 16384          // 128 rows x 128 B (bf16)
#define B_PITCH 272         // 64 fp32 + 16B pad (68 words; 68 mod 32 = 4)
#define B_ST (64 * B_PITCH) // 17408
#define STAGE (A_ST + B_ST) // 33792
#define NSTG 3
#define GEMM_SMEM (NSTG * STAGE)   // 101376

__global__ __launch_bounds__(256, 2) void gemm_kernel(const float* __restrict__ wv) {
  extern __shared__ __align__(16) char smraw[];
  const unsigned sbase = (unsigned)__cvta_generic_to_shared(smraw);

  const int tid = threadIdx.x;
  const int lane = tid & 31;
  const int warp = tid >> 5;
  const int wm = warp & 3;   // M group: rows 32*wm..
  const int wn = warp >> 2;  // N group: cols 32*wn..
  const int bid = blockIdx.x;
  const int kt = bid >> 7;                 // k-half: 0 or 1
  const int n0 = (bid & 127) * 64;
  const int kbase = kt * 1024;             // element k offset
  float* outbuf = kt ? g_part1 : g_part0;

  float c[2][4][4];
#pragma unroll
  for (int mi = 0; mi < 2; mi++)
#pragma unroll
    for (int ni = 0; ni < 4; ni++)
#pragma unroll
      for (int q = 0; q < 4; q++) c[mi][ni][q] = 0.f;

  // per-thread cp.async geometry (fixed across iterations)
  const int arow = tid >> 3, ach = tid & 7;          // A: +256 stride in idx
  const int brow = tid >> 4, bf4 = tid & 15;

  auto issue = [&](int it) {
    const int k0 = kbase + it * 64;
    const unsigned st = sbase + (it % NSTG) * STAGE;
    // A: 4 x 16B per thread (swizzled bf16 rows)
#pragma unroll
    for (int i = 0; i < 4; i++) {
      int row = arow + 32 * i;                        // (tid+256i)>>3
      unsigned dst = st + row * 128 + 16 * (ach ^ (row & 7));
      cpasync16(dst, &g_xbar[row * ND + k0 + ach * 8]);
    }
    // B: 4 x 16B per thread (fp32 rows, pitch 272B)
#pragma unroll
    for (int i = 0; i < 4; i++) {
      int row = brow + 16 * i;                        // (tid+256i)>>4
      unsigned dst = st + A_ST + row * B_PITCH + bf4 * 16;
      cpasync16(dst, &wv[(size_t)(k0 + row) * NN + n0 + bf4 * 4]);
    }
    cpcommit();
  };

  const int lm = lane & 15;
  const int lh = lane >> 4;
  const int bn_off = (wn * 32 + (lane >> 2)) * 4;     // byte offset of n in B row
  const int bk_row = (lane & 3) * 2;                  // k row within 16-group

  auto compute = [&](int it) {
    const unsigned st = sbase + (it % NSTG) * STAGE;
    const unsigned bB = st + A_ST;
#pragma unroll
    for (int ks = 0; ks < 4; ks++) {
      unsigned a[2][4];
#pragma unroll
      for (int mi = 0; mi < 2; mi++) {
        int mrow = wm * 32 + mi * 16 + lm;
        int kc = ks * 2 + lh;
        unsigned s = st + mrow * 128 + 16 * (kc ^ (mrow & 7));
        ldsm_x4(a[mi][0], a[mi][1], a[mi][2], a[mi][3], s);
      }
      // B fragments: LDS.32 + cvt (conflict-free via 272B pitch)
      unsigned bf[4][2];
      const unsigned kb = bB + (ks * 16 + bk_row) * B_PITCH + bn_off;
#pragma unroll
      for (int ni = 0; ni < 4; ni++) {
        float f0 = lds_f32(kb + ni * 32);
        float f1 = lds_f32(kb + ni * 32 + B_PITCH);
        float f2 = lds_f32(kb + ni * 32 + 8 * B_PITCH);
        float f3 = lds_f32(kb + ni * 32 + 9 * B_PITCH);
        __nv_bfloat162 p0 = __floats2bfloat162_rn(f0, f1);
        __nv_bfloat162 p1 = __floats2bfloat162_rn(f2, f3);
        bf[ni][0] = *reinterpret_cast<unsigned*>(&p0);
        bf[ni][1] = *reinterpret_cast<unsigned*>(&p1);
      }
#pragma unroll
      for (int mi = 0; mi < 2; mi++)
#pragma unroll
        for (int ni = 0; ni < 4; ni++)
          mma16816(c[mi][ni][0], c[mi][ni][1], c[mi][ni][2], c[mi][ni][3],
                   a[mi][0], a[mi][1], a[mi][2], a[mi][3],
                   bf[ni][0], bf[ni][1]);
    }
  };

  issue(0);
  issue(1);
#pragma unroll 1
  for (int it = 0; it < 16; it++) {
    if (it + 2 < 16) issue(it + 2);
    if (it < 14)      cpwait<2>();
    else if (it == 14) cpwait<1>();
    else               cpwait<0>();
    __syncthreads();          // all copies for stage 'it' visible to all
    compute(it);
    __syncthreads();          // all reads done before stage reuse
  }

  // epilogue: store SIGNED partials (abs after the k-halves add)
#pragma unroll
  for (int mi = 0; mi < 2; mi++) {
#pragma unroll
    for (int ni = 0; ni < 4; ni++) {
      int m = wm * 32 + mi * 16 + (lane >> 2);
      int n = n0 + wn * 32 + ni * 8 + (lane & 3) * 2;
      *reinterpret_cast<float2*>(&outbuf[(size_t)m * NN + n]) =
          make_float2(c[mi][ni][0], c[mi][ni][1]);
      *reinterpret_cast<float2*>(&outbuf[(size_t)(m + 8) * NN + n]) =
          make_float2(c[mi][ni][2], c[mi][ni][3]);
    }
  }
}

// =================================================================
// Kernel C: per-batch marg scan (|p0+p1|), label gather, 4x4 chains,
// loss_b, fused last-block mean reduction -> out[0]
// =================================================================
__global__ __launch_bounds__(128) void finalize_kernel(
    const int* __restrict__ labels, float* __restrict__ out) {
  const int b = blockIdx.x;
  const int tid = threadIdx.x;
  const float* p0 = g_part0 + (size_t)b * NN;
  const float* p1 = g_part1 + (size_t)b * NN;

  __shared__ float part[8][16];
  __shared__ float marg[16];

  const int ij = tid & 15, vs = tid >> 4;
  const int i = ij >> 2, j = ij & 3;
  float s = 0.f;
  for (int v = vs * 64; v < vs * 64 + 64; v++) {
    int idx = i * (NV * NR) + v * NR + j;
    s += fabsf(p0[idx] + p1[idx]);
  }
  part[vs][ij] = s;
  __syncthreads();
  if (tid < 16) {
    float m = 0.f;
#pragma unroll
    for (int w = 0; w < 8; w++) m += part[w][tid];
    marg[tid] = m;
  }
  __syncthreads();

  if (tid == 0) {
    float res[16], tmp[16], mt[16];
    int lab = labels[b * NT];
#pragma unroll
    for (int q = 0; q < 16; q++) {
      int idx = (q >> 2) * (NV * NR) + lab * NR + (q & 3);
      res[q] = fabsf(p0[idx] + p1[idx]);
    }
    for (int t = 1; t < NT; t++) {
      lab = labels[b * NT + t];
#pragma unroll
      for (int q = 0; q < 16; q++) {
        int idx = (q >> 2) * (NV * NR) + lab * NR + (q & 3);
        mt[q] = fabsf(p0[idx] + p1[idx]);
      }
#pragma unroll
      for (int ii = 0; ii < 4; ii++)
#pragma unroll
        for (int jj = 0; jj < 4; jj++) {
          float acc = 0.f;
#pragma unroll
          for (int kk = 0; kk < 4; kk++) acc += res[ii * 4 + kk] * mt[kk * 4 + jj];
          tmp[ii * 4 + jj] = acc;
        }
#pragma unroll
      for (int q = 0; q < 16; q++) res[q] = tmp[q];
    }
    const float* al = g_alpha + b * 4;
    const float* be = g_beta + b * 4;
    float u = 0.f;
#pragma unroll
    for (int ii = 0; ii < 4; ii++)
#pragma unroll
      for (int jj = 0; jj < 4; jj++) u += al[ii] * res[ii * 4 + jj] * be[jj];

    float zc[16];
#pragma unroll
    for (int q = 0; q < 16; q++) zc[q] = marg[q];
    for (int t = 0; t < NT; t++) {   // zc = marg^(T+1)
#pragma unroll
      for (int ii = 0; ii < 4; ii++)
#pragma unroll
        for (int jj = 0; jj < 4; jj++) {
          float acc = 0.f;
#pragma unroll
          for (int kk = 0; kk < 4; kk++) acc += zc[ii * 4 + kk] * marg[kk * 4 + jj];
          tmp[ii * 4 + jj] = acc;
        }
#pragma unroll
      for (int q = 0; q < 16; q++) zc[q] = tmp[q];
    }
    float z = 0.f;
#pragma unroll
    for (int ii = 0; ii < 4; ii++)
#pragma unroll
      for (int jj = 0; jj < 4; jj++) z += al[ii] * zc[ii * 4 + jj] * be[jj];

    g_loss[b] = logf(z) - logf(u);   // = -log(u/z)
  }

  // ---- fused mean reduction: last block to finish does it ----
  __shared__ int is_last;
  if (tid == 0) {
    __threadfence();
    int prev = atomicAdd(&g_done_cnt, 1);
    is_last = (prev == NB - 1);
  }
  __syncthreads();
  if (is_last) {
    __threadfence();
    float v = g_loss[tid];
#pragma unroll
    for (int o = 16; o; o >>= 1) v += __shfl_xor_sync(0xFFFFFFFFu, v, o);
    __shared__ float sw[4];
    if ((tid & 31) == 0) sw[tid >> 5] = v;
    __syncthreads();
    if (tid == 0) {
      out[0] = (sw[0] + sw[1] + sw[2] + sw[3]) * (1.0f / 128.0f);
      atomicExch(&g_done_cnt, 0);   // reset for next graph replay
    }
  }
}

// =================================================================
extern "C" void kernel_launch(void* const* d_in, const int* in_sizes, int n_in,
                              void* d_out, int out_size) {
  const float* x      = (const float*)d_in[0];   // [128, 8, 2048]
  const int*   labels = (const int*)  d_in[1];   // [128, 8]
  const float* wa     = (const float*)d_in[2];   // [2048, 4]
  const float* wb     = (const float*)d_in[3];   // [2048, 4]
  const float* wv     = (const float*)d_in[4];   // [2048, 8192]
  float* out = (float*)d_out;

  static int smem_set = 0;
  if (!smem_set) {
    cudaFuncSetAttribute(gemm_kernel,
                         cudaFuncAttributeMaxDynamicSharedMemorySize, GEMM_SMEM);
    smem_set = 1;
  }

  prep_kernel<<<NB, 512>>>(x, wa, wb);
  gemm_kernel<<<2 * (NN / 64), 256, GEMM_SMEM>>>(wv);
  finalize_kernel<<<NB, 128>>>(labels, out);
}